// round 13
// baseline (speedup 1.0000x reference)
#include <cuda_runtime.h>
#include <cuda_fp16.h>
#include <cstdint>
#include <cstddef>

#define TB 1024
#define PREP_TB 256
#define BATCH 256
#define ROWS 2
#define NGROUPS (BATCH / ROWS)       // 128 CTAs
#define TENC 200
#define TD 200
#define DMODEL 256
#define INR 400
#define PM_ROWS 16
#define PM_BLOCKS (BATCH * TENC / PM_ROWS)          // 3200
#define ENC_ELEMS (BATCH * TENC * DMODEL)           // 13107200
#define ENC_CVT_BLOCKS (ENC_ELEMS / (PREP_TB * 8))  // 6400

// ------------------------- persistent device scratch -------------------------
__device__ __align__(16) __half g_pmh[ENC_ELEMS];   // processed_memory fp16
__device__ __align__(16) __half g_ench[ENC_ELEMS];  // encoder outputs fp16

// fp16 weights in mma B-fragment layout: [ktile][ntile][lane] uint2
// element count = K*OP/4 uint2 per matrix
__device__ __align__(16) uint2 g_fWp1[400 * 256 / 4];
__device__ __align__(16) uint2 g_fWaih[384 * 768 / 4];
__device__ __align__(16) uint2 g_fWahh[256 * 768 / 4];
__device__ __align__(16) uint2 g_fWq[256 * 256 / 4];
__device__ __align__(16) uint2 g_fWproj[512 * 256 / 4];
__device__ __align__(16) uint2 g_fWd1i[256 * 768 / 4];
__device__ __align__(16) uint2 g_fWd1h[256 * 768 / 4];
__device__ __align__(16) uint2 g_fWd2i[256 * 768 / 4];
__device__ __align__(16) uint2 g_fWd2h[256 * 768 / 4];
__device__ __align__(16) uint2 g_fWmel[256 * 512 / 4];   // O padded 400->512
// prenet2 keeps the FFMA path: [K][O] fp16
__device__ __align__(16) __half g_tWp2[256 * 128];

// ------------------------- helpers -------------------------
__device__ __forceinline__ float tanh_approx(float x) {
    float y;
    asm("tanh.approx.f32 %0, %1;" : "=f"(y) : "f"(x));
    return y;
}
__device__ __forceinline__ float sigmoidf_(float x) {
    return 1.0f / (1.0f + __expf(-x));
}
__device__ __forceinline__ unsigned long long f2pack(float x, float y) {
    unsigned long long d;
    asm("mov.b64 %0, {%1, %2};" : "=l"(d) : "f"(x), "f"(y));
    return d;
}
__device__ __forceinline__ float2 f2unpack(unsigned long long v) {
    float2 r;
    asm("mov.b64 {%0, %1}, %2;" : "=f"(r.x), "=f"(r.y) : "l"(v));
    return r;
}
__device__ __forceinline__ unsigned long long ffma2(unsigned long long a,
                                                    unsigned long long b,
                                                    unsigned long long c) {
    unsigned long long d;
    asm("fma.rn.f32x2 %0, %1, %2, %3;" : "=l"(d) : "l"(a), "l"(b), "l"(c));
    return d;
}
__device__ __forceinline__ uint32_t pack2h(float lo, float hi) {
    __half2 h = __floats2half2_rn(lo, hi);
    return *reinterpret_cast<uint32_t*>(&h);
}
// m16n8k16 row.col f32 accum
__device__ __forceinline__ void mma16816(float& c0, float& c1, float& c2, float& c3,
                                         uint32_t a0, uint32_t a1, uint32_t a2,
                                         uint32_t a3, uint32_t b0, uint32_t b1) {
    asm volatile(
        "mma.sync.aligned.m16n8k16.row.col.f32.f16.f16.f32 "
        "{%0,%1,%2,%3}, {%4,%5,%6,%7}, {%8,%9}, {%0,%1,%2,%3};"
        : "+f"(c0), "+f"(c1), "+f"(c2), "+f"(c3)
        : "r"(a0), "r"(a1), "r"(a2), "r"(a3), "r"(b0), "r"(b1));
}

// ------------------------- prep kernel ---------------------------------------
struct PrepArgs {
    const float* fsrc[10];
    uint2* fdst[10];
    int fK[10], fNT[10], fO[10];
    int fstart[11];
    const float* p2src;
    __half* p2dst;
    const float* enc;
    const float* memW;
    __half* pm;
    __half* ench;
};

#define P2_BLOCKS 128   // 256*128/256

__global__ void __launch_bounds__(PREP_TB) prep_kernel(PrepArgs a) {
    int bid = blockIdx.x;
    if (bid < PM_BLOCKS) {
        __shared__ __align__(16) float se[PM_ROWS][DMODEL];
        size_t row0 = (size_t)bid * PM_ROWS;
        for (int i = threadIdx.x; i < PM_ROWS * DMODEL; i += PREP_TB)
            se[i >> 8][i & 255] = a.enc[row0 * DMODEL + i];
        __syncthreads();
        int o = threadIdx.x;
        float acc[PM_ROWS];
#pragma unroll
        for (int r = 0; r < PM_ROWS; ++r) acc[r] = 0.f;
        const float4* W4 = reinterpret_cast<const float4*>(a.memW + (size_t)o * DMODEL);
#pragma unroll 4
        for (int k4 = 0; k4 < DMODEL / 4; ++k4) {
            float4 w = __ldg(&W4[k4]);
#pragma unroll
            for (int r = 0; r < PM_ROWS; ++r) {
                const float* e = &se[r][k4 * 4];
                float s = acc[r];
                s = fmaf(w.x, e[0], s); s = fmaf(w.y, e[1], s);
                s = fmaf(w.z, e[2], s); s = fmaf(w.w, e[3], s);
                acc[r] = s;
            }
        }
#pragma unroll
        for (int r = 0; r < PM_ROWS; ++r)
            a.pm[(row0 + r) * DMODEL + o] = __float2half_rn(acc[r]);
        return;
    }
    int tb = bid - PM_BLOCKS;
    if (tb < P2_BLOCKS) {
        // prenet2 transpose-convert: [O=128][K=256] fp32 -> [K][128] fp16
        int local = tb * PREP_TB + threadIdx.x;
        int k = local >> 7, o = local & 127;
        a.p2dst[local] = __float2half_rn(a.p2src[(size_t)o * 256 + k]);
        return;
    }
    int tb2 = tb - P2_BLOCKS;
    if (tb2 < a.fstart[10]) {
        // fragment prep
        int m = 0;
#pragma unroll
        for (int j = 0; j < 10; ++j)
            if (tb2 >= a.fstart[j + 1]) m = j + 1;
        int i = (tb2 - a.fstart[m]) * PREP_TB + threadIdx.x;
        int lane = i & 31, t2 = i >> 5;
        int NT = a.fNT[m];
        int nt = t2 % NT, kt = t2 / NT;
        int K = a.fK[m], O = a.fO[m];
        int n = nt * 8 + (lane >> 2);
        int kb = kt * 16 + (lane & 3) * 2;
        const float* src = a.fsrc[m];
        float e0 = 0.f, e1 = 0.f, e2 = 0.f, e3 = 0.f;
        if (n < O) {
            const float* sp = src + (size_t)n * K;
            e0 = sp[kb]; e1 = sp[kb + 1];
            e2 = sp[kb + 8]; e3 = sp[kb + 9];
        }
        uint2 v;
        v.x = pack2h(e0, e1);
        v.y = pack2h(e2, e3);
        a.fdst[m][i] = v;
        return;
    }
    // enc fp32 -> fp16
    int e = tb2 - a.fstart[10];
    size_t i0 = ((size_t)e * PREP_TB + threadIdx.x) * 8;
    const float4* S4 = reinterpret_cast<const float4*>(a.enc + i0);
    float4 f0 = S4[0], f1 = S4[1];
    uint4 outv;
    outv.x = pack2h(f0.x, f0.y);
    outv.y = pack2h(f0.z, f0.w);
    outv.z = pack2h(f1.x, f1.y);
    outv.w = pack2h(f1.z, f1.w);
    *reinterpret_cast<uint4*>(a.ench + i0) = outv;
}

// -------------- mma gemv task (one warp, 256 outputs, 2 rows) ----------------
// frag: B-fragment weights; NT = OP/8; x2[k]=(row0,row1) fp32 in smem.
// kt0 = first k-tile (16 k each), KT = tiles per task (1 or 2).
// pp -> partials [2][256] (row-major, same as before).
template <int KT>
__device__ __forceinline__ void gemv_mma(const uint2* __restrict__ frag, int NT,
                                         const float2* __restrict__ x2,
                                         int o0, int kt0,
                                         float* __restrict__ pp) {
    const int lane = threadIdx.x & 31;
    const int tg = (lane & 3) * 2;
    const bool r1 = (lane >> 2) == 1;   // D row 1 lanes use x row1
    uint32_t aLo[KT], aHi[KT];
#pragma unroll
    for (int kt = 0; kt < KT; ++kt) {
        int kk = (kt0 + kt) * 16 + tg;
        float2 xa = x2[kk], xb = x2[kk + 1];
        float2 xc = x2[kk + 8], xd = x2[kk + 9];
        aLo[kt] = pack2h(r1 ? xa.y : xa.x, r1 ? xb.y : xb.x);
        aHi[kt] = pack2h(r1 ? xc.y : xc.x, r1 ? xd.y : xd.x);
    }
    const uint2* fb = frag + ((size_t)kt0 * NT + (o0 >> 3)) * 32 + lane;
#pragma unroll 8
    for (int nt = 0; nt < 32; ++nt) {
        float c0 = 0.f, c1 = 0.f, c2 = 0.f, c3 = 0.f;
#pragma unroll
        for (int kt = 0; kt < KT; ++kt) {
            uint2 b = __ldg(fb + ((size_t)kt * NT + nt) * 32);
            mma16816(c0, c1, c2, c3, aLo[kt], aLo[kt], aHi[kt], aHi[kt], b.x, b.y);
        }
        if (lane < 8) {
            int r = lane >> 2;
            *reinterpret_cast<float2*>(pp + r * 256 + nt * 8 + tg) =
                make_float2(c0, c1);
        }
    }
}

// VEC8-layout partial reduce: tasks (o>>8)*NC + c starting at slot tb
template <int NC>
__device__ __forceinline__ float redV8(const float* __restrict__ part, int tb,
                                       int o, int row) {
    const float* p = part + (size_t)(tb + (o >> 8) * NC) * 512 + row * 256 + (o & 255);
    float s = 0.f;
#pragma unroll
    for (int c = 0; c < NC; ++c) s += p[c * 512];
    return s;
}

// -------------- gemv task VEC=4 (128 outputs) for prenet2 --------------------
__device__ __forceinline__ void gemv_task4(const __half* __restrict__ WT, int Ostride,
                                           const float2* __restrict__ x2,
                                           int o0, int k0, int k1,
                                           float* __restrict__ pp) {
    const int lane = threadIdx.x & 31;
    const __half* base = WT + (size_t)k0 * Ostride + o0 + lane * 4;
    unsigned long long a0[2], a1[2];
    a0[0] = a0[1] = a1[0] = a1[1] = 0ull;
#pragma unroll 4
    for (int k = k0; k < k1; ++k) {
        uint2 wv = __ldg(reinterpret_cast<const uint2*>(base));
        base += Ostride;
        float2 w01 = __half22float2(*reinterpret_cast<__half2*>(&wv.x));
        float2 w23 = __half22float2(*reinterpret_cast<__half2*>(&wv.y));
        float2 xv = x2[k];
        unsigned long long xr0 = f2pack(xv.x, xv.x);
        unsigned long long xr1 = f2pack(xv.y, xv.y);
        unsigned long long wA = f2pack(w01.x, w01.y);
        unsigned long long wB = f2pack(w23.x, w23.y);
        a0[0] = ffma2(wA, xr0, a0[0]);
        a1[0] = ffma2(wA, xr1, a1[0]);
        a0[1] = ffma2(wB, xr0, a0[1]);
        a1[1] = ffma2(wB, xr1, a1[1]);
    }
    float2 p0 = f2unpack(a0[0]), p1 = f2unpack(a0[1]);
    float2 q0 = f2unpack(a1[0]), q1 = f2unpack(a1[1]);
    reinterpret_cast<float4*>(pp)[lane] = make_float4(p0.x, p0.y, p1.x, p1.y);
    reinterpret_cast<float4*>(pp + 128)[lane] = make_float4(q0.x, q0.y, q1.x, q1.y);
}

template <int NC>
__device__ __forceinline__ float redV4(const float* __restrict__ part, int tb,
                                       int o, int row) {
    const float* p = part + (size_t)(tb + (o >> 7) * NC) * 256 + row * 128 + (o & 127);
    float s = 0.f;
#pragma unroll
    for (int c = 0; c < NC; ++c) s += p[c * 256];
    return s;
}

// ------------------------- shared memory layout ----------------------------
struct __align__(16) SD {
    float part[60 * 512];     // 122880 B partials (also ctx scratch)
    float2 in2[400];
    float2 p12[256];
    float2 x2[384];           // [0:128)=prenet2, [128:384)=ctx
    float2 cat2[512];
    float2 d2[256];
    float2 ah2[256];
    float2 h12[256];
    float2 h22[256];
    float qT[2][256];
    float sc[2][TENC];
    float v[256];
    int len_s[2];
    float b_p1[256]; float b_p2[128];
    float b_aih[768]; float b_ahh[768];
    float b_proj[256];
    float b_d1i[768]; float b_d1h[768];
    float b_d2i[768]; float b_d2h[768];
    float b_mel[400];
};

// ------------------------- main persistent decoder -------------------------
__global__ void __launch_bounds__(TB, 1) decoder_kernel(
    const float* __restrict__ inputs,
    const int* __restrict__ memlen,
    const float* __restrict__ gb_p1, const float* __restrict__ gb_p2,
    const float* __restrict__ gb_aih, const float* __restrict__ gb_ahh,
    const float* __restrict__ vW,
    const float* __restrict__ gb_proj,
    const float* __restrict__ gb_d1i, const float* __restrict__ gb_d1h,
    const float* __restrict__ gb_d2i, const float* __restrict__ gb_d2h,
    const float* __restrict__ gb_mel,
    float* __restrict__ out, int write_align) {
    extern __shared__ unsigned char smem_raw[];
    SD* s = reinterpret_cast<SD*>(smem_raw);

    const int tid = threadIdx.x;
    const int wid = tid >> 5;
    const int lane = tid & 31;
    const int b0 = blockIdx.x * ROWS;

    // init state + biases + zero first input
    {
        float2 z2 = make_float2(0.f, 0.f);
        if (tid < 256) {
            s->ah2[tid] = z2; s->h12[tid] = z2; s->h22[tid] = z2;
            s->x2[128 + tid] = z2;
            s->v[tid] = vW[tid];
            s->b_p1[tid] = gb_p1[tid];
            s->b_proj[tid] = gb_proj[tid];
        }
        if (tid >= 256 && tid < 384) s->b_p2[tid - 256] = gb_p2[tid - 256];
        if (tid < 768) {
            s->b_aih[tid] = gb_aih[tid]; s->b_ahh[tid] = gb_ahh[tid];
            s->b_d1i[tid] = gb_d1i[tid]; s->b_d1h[tid] = gb_d1h[tid];
            s->b_d2i[tid] = gb_d2i[tid]; s->b_d2h[tid] = gb_d2h[tid];
        }
        if (tid >= 512 && tid < 912) s->b_mel[tid - 512] = gb_mel[tid - 512];
        if (tid < 2) s->len_s[tid] = memlen[b0 + tid];
        if (tid < 400) s->in2[tid] = z2;   // teacher input at t=0 is zeros
    }
    __syncthreads();

    float* outMel = out;
    float* outAl = out + (size_t)BATCH * TD * INR;

    for (int t = 0; t < TD; ++t) {
        // ---- A: prenet1 (O=256, K=400): 25 tasks, 1 k-tile each ----
        if (wid < 25)
            gemv_mma<1>(g_fWp1, 32, s->in2, 0, wid, s->part + (size_t)wid * 512);
        __syncthreads();
        if (tid < 512) {
            int o = tid & 255, row = tid >> 8;
            float r = redV8<25>(s->part, 0, o, row) + s->b_p1[o];
            reinterpret_cast<float*>(&s->p12[o])[row] = fmaxf(r, 0.f);
        } else if (t + 1 < TD) {
            // load teacher-forced input for NEXT step
            for (int i = tid - 512; i < 2 * INR; i += 512) {
                int row = i / INR, o = i - row * INR;
                reinterpret_cast<float*>(&s->in2[o])[row] =
                    inputs[((size_t)(b0 + row) * 1000 + (size_t)t * 5) * 80 + o];
            }
        }
        __syncthreads();

        // ---- B: prenet2 (O=128, K=256): VEC4 FFMA, 32 chunks CH=8 ----
        gemv_task4(g_tWp2, 128, s->p12, 0, wid * 8, wid * 8 + 8,
                   s->part + (size_t)wid * 256);
        __syncthreads();
        if (tid < 256) {
            int o = tid & 127, row = tid >> 7;
            float r = redV4<32>(s->part, 0, o, row) + s->b_p2[o];
            reinterpret_cast<float*>(&s->x2[o])[row] = fmaxf(r, 0.f);
        }
        __syncthreads();

        // ---- C: attn GRU: gi 36 tasks (3 o-tiles x 12 chunks of 2kt, K=384)
        //                  + gh 24 tasks (3 x 8 chunks of 2kt, K=256) ----
        for (int task = wid; task < 60; task += 32) {
            if (task < 36) {
                int ot = task / 12, c = task - ot * 12;
                gemv_mma<2>(g_fWaih, 96, s->x2, ot * 256, c * 2,
                            s->part + (size_t)task * 512);
            } else {
                int t2 = task - 36;
                int ot = t2 >> 3, c = t2 & 7;
                gemv_mma<2>(g_fWahh, 96, s->ah2, ot * 256, c * 2,
                            s->part + (size_t)task * 512);
            }
        }
        __syncthreads();
        if (tid < 512) {
            int o = tid & 255, row = tid >> 8;
            float ir = redV8<12>(s->part, 0, o, row) + s->b_aih[o];
            float iz = redV8<12>(s->part, 0, 256 + o, row) + s->b_aih[256 + o];
            float in = redV8<12>(s->part, 0, 512 + o, row) + s->b_aih[512 + o];
            float hr = redV8<8>(s->part, 36, o, row) + s->b_ahh[o];
            float hz = redV8<8>(s->part, 36, 256 + o, row) + s->b_ahh[256 + o];
            float hn = redV8<8>(s->part, 36, 512 + o, row) + s->b_ahh[512 + o];
            float hp = reinterpret_cast<float*>(&s->ah2[o])[row];
            float rg = sigmoidf_(ir + hr);
            float z = sigmoidf_(iz + hz);
            float n = tanhf(in + rg * hn);
            float h = (1.f - z) * n + z * hp;
            reinterpret_cast<float*>(&s->ah2[o])[row] = h;
            reinterpret_cast<float*>(&s->cat2[o])[row] = h;
        }
        __syncthreads();

        // ---- D: query (O=256, K=256): 16 tasks, 1 kt each ----
        if (wid < 16)
            gemv_mma<1>(g_fWq, 32, s->ah2, 0, wid, s->part + (size_t)wid * 512);
        __syncthreads();
        if (tid < 512) {
            int o = tid & 255, row = tid >> 8;
            s->qT[row][o] = redV8<16>(s->part, 0, o, row);
        }
        __syncthreads();

        // ---- E: Bahdanau scores (fp16 pm) ----
        {
            const float4* V = reinterpret_cast<const float4*>(s->v);
            float4 v0 = V[lane * 2], v1 = V[lane * 2 + 1];
            for (int task = wid; task < 2 * TENC; task += 32) {
                int row = task & 1, tt = task >> 1;
                const uint4* P = reinterpret_cast<const uint4*>(
                    g_pmh + ((size_t)(b0 + row) * TENC + tt) * DMODEL);
                uint4 pv = __ldg(&P[lane]);
                float2 p0 = __half22float2(*reinterpret_cast<__half2*>(&pv.x));
                float2 p1 = __half22float2(*reinterpret_cast<__half2*>(&pv.y));
                float2 p2 = __half22float2(*reinterpret_cast<__half2*>(&pv.z));
                float2 p3 = __half22float2(*reinterpret_cast<__half2*>(&pv.w));
                const float4* Q = reinterpret_cast<const float4*>(s->qT[row]);
                float4 q0 = Q[lane * 2], q1 = Q[lane * 2 + 1];
                float acc = 0.f;
                acc += v0.x * tanh_approx(p0.x + q0.x);
                acc += v0.y * tanh_approx(p0.y + q0.y);
                acc += v0.z * tanh_approx(p1.x + q0.z);
                acc += v0.w * tanh_approx(p1.y + q0.w);
                acc += v1.x * tanh_approx(p2.x + q1.x);
                acc += v1.y * tanh_approx(p2.y + q1.y);
                acc += v1.z * tanh_approx(p3.x + q1.z);
                acc += v1.w * tanh_approx(p3.y + q1.w);
#pragma unroll
                for (int sh = 16; sh; sh >>= 1) acc += __shfl_xor_sync(0xffffffffu, acc, sh);
                if (lane == 0)
                    s->sc[row][tt] = (tt < s->len_s[row]) ? acc : -1e9f;
            }
        }
        __syncthreads();

        // ---- F: softmax per row (warps 0..1) + alignment output ----
        if (wid < 2) {
            int row = wid;
            float m = -1e30f;
            for (int i = lane; i < TENC; i += 32) m = fmaxf(m, s->sc[row][i]);
#pragma unroll
            for (int sh = 16; sh; sh >>= 1) m = fmaxf(m, __shfl_xor_sync(0xffffffffu, m, sh));
            float sum = 0.f;
            for (int i = lane; i < TENC; i += 32) {
                float e = __expf(s->sc[row][i] - m);
                s->sc[row][i] = e;
                sum += e;
            }
#pragma unroll
            for (int sh = 16; sh; sh >>= 1) sum += __shfl_xor_sync(0xffffffffu, sum, sh);
            float inv = 1.f / sum;
            float* ao = outAl + ((size_t)(b0 + row) * TD + t) * TENC;
            for (int i = lane; i < TENC; i += 32) {
                float a = s->sc[row][i] * inv;
                s->sc[row][i] = a;
                if (write_align) ao[i] = a;
            }
        }
        __syncthreads();

        // ---- G: attention context (fp16 enc): g(64) x row(2) x ts(8x25) ----
        {
            int g = tid & 63, row = (tid >> 6) & 1, ts = tid >> 7;
            const uint2* E = reinterpret_cast<const uint2*>(
                                 g_ench + (size_t)(b0 + row) * TENC * DMODEL);
            const float* scp = s->sc[row];
            float4 acc = make_float4(0.f, 0.f, 0.f, 0.f);
            int tt0 = ts * 25;
#pragma unroll 5
            for (int tt = tt0; tt < tt0 + 25; ++tt) {
                float a = scp[tt];
                uint2 ev = __ldg(&E[tt * 64 + g]);
                float2 e0 = __half22float2(*reinterpret_cast<__half2*>(&ev.x));
                float2 e1 = __half22float2(*reinterpret_cast<__half2*>(&ev.y));
                acc.x = fmaf(a, e0.x, acc.x);
                acc.y = fmaf(a, e0.y, acc.y);
                acc.z = fmaf(a, e1.x, acc.z);
                acc.w = fmaf(a, e1.y, acc.w);
            }
            reinterpret_cast<float4*>(s->part)[(ts * 2 + row) * 64 + g] = acc;
        }
        __syncthreads();
        if (tid < 512) {
            int o = tid & 255, row = tid >> 8;
            int gg = o >> 2, comp = o & 3;
            const float* pf = s->part;
            float sv = 0.f;
#pragma unroll
            for (int ts = 0; ts < 8; ++ts)
                sv += pf[((ts * 2 + row) * 64 + gg) * 4 + comp];
            reinterpret_cast<float*>(&s->x2[128 + o])[row] = sv;
            reinterpret_cast<float*>(&s->cat2[256 + o])[row] = sv;
        }
        __syncthreads();

        // ---- H: proj (O=256, K=512): 32 tasks, 1 kt each ----
        gemv_mma<1>(g_fWproj, 32, s->cat2, 0, wid, s->part + (size_t)wid * 512);
        __syncthreads();
        if (tid < 512) {
            int o = tid & 255, row = tid >> 8;
            float r = redV8<32>(s->part, 0, o, row) + s->b_proj[o];
            reinterpret_cast<float*>(&s->d2[o])[row] = r;
        }
        __syncthreads();

        // ---- I/J: decoder GRUs: gi 24 + gh 24 tasks (3 o-tiles x 8 x 2kt) ----
#pragma unroll
        for (int gru = 0; gru < 2; ++gru) {
            const uint2* Wi = gru ? g_fWd2i : g_fWd1i;
            const uint2* Wh = gru ? g_fWd2h : g_fWd1h;
            const float* bi = gru ? s->b_d2i : s->b_d1i;
            const float* bh = gru ? s->b_d2h : s->b_d1h;
            float2* hstate = gru ? s->h22 : s->h12;
            for (int task = wid; task < 48; task += 32) {
                if (task < 24) {
                    int ot = task >> 3, c = task & 7;
                    gemv_mma<2>(Wi, 96, s->d2, ot * 256, c * 2,
                                s->part + (size_t)task * 512);
                } else {
                    int t2 = task - 24;
                    int ot = t2 >> 3, c = t2 & 7;
                    gemv_mma<2>(Wh, 96, hstate, ot * 256, c * 2,
                                s->part + (size_t)task * 512);
                }
            }
            __syncthreads();
            if (tid < 512) {
                int o = tid & 255, row = tid >> 8;
                float ir = redV8<8>(s->part, 0, o, row) + bi[o];
                float iz = redV8<8>(s->part, 0, 256 + o, row) + bi[256 + o];
                float in = redV8<8>(s->part, 0, 512 + o, row) + bi[512 + o];
                float hr = redV8<8>(s->part, 24, o, row) + bh[o];
                float hz = redV8<8>(s->part, 24, 256 + o, row) + bh[256 + o];
                float hn = redV8<8>(s->part, 24, 512 + o, row) + bh[512 + o];
                float hp = reinterpret_cast<float*>(&hstate[o])[row];
                float rg = sigmoidf_(ir + hr);
                float z = sigmoidf_(iz + hz);
                float n = tanhf(in + rg * hn);
                float h = (1.f - z) * n + z * hp;
                reinterpret_cast<float*>(&hstate[o])[row] = h;
                reinterpret_cast<float*>(&s->d2[o])[row] += h;
            }
            __syncthreads();
        }

        // ---- K: mel (O=512 pad, K=256): 2 o-tiles x 16 kt = 32 tasks ----
        {
            int ot = wid >> 4, c = wid & 15;
            gemv_mma<1>(g_fWmel, 64, s->d2, ot * 256, c,
                        s->part + (size_t)wid * 512);
        }
        __syncthreads();
        if (tid < 2 * INR) {
            int row = tid / INR, o = tid - row * INR;
            float r = redV8<16>(s->part, 0, o, row) + s->b_mel[o];
            outMel[((size_t)(b0 + row) * TD + t) * INR + o] = r;
        }
        __syncthreads();
    }
}

// ------------------------- launch -------------------------
extern "C" void kernel_launch(void* const* d_in, const int* in_sizes, int n_in,
                              void* d_out, int out_size) {
    const float* enc = (const float*)d_in[0];
    const float* inputs = (const float*)d_in[1];
    const int* memlen = (const int*)d_in[2];

    PrepArgs a;
    // matrices: p1, aih, ahh, q, proj, d1i, d1h, d2i, d2h, mel
    static const int srcIdx[10] = {3, 7, 9, 12, 14, 16, 18, 20, 22, 24};
    static const int Karr[10] = {400, 384, 256, 256, 512, 256, 256, 256, 256, 256};
    static const int Oarr[10] = {256, 768, 768, 256, 256, 768, 768, 768, 768, 400};
    static const int OParr[10] = {256, 768, 768, 256, 256, 768, 768, 768, 768, 512};

    void* dsts[10];
    cudaGetSymbolAddress(&dsts[0], g_fWp1);
    cudaGetSymbolAddress(&dsts[1], g_fWaih);
    cudaGetSymbolAddress(&dsts[2], g_fWahh);
    cudaGetSymbolAddress(&dsts[3], g_fWq);
    cudaGetSymbolAddress(&dsts[4], g_fWproj);
    cudaGetSymbolAddress(&dsts[5], g_fWd1i);
    cudaGetSymbolAddress(&dsts[6], g_fWd1h);
    cudaGetSymbolAddress(&dsts[7], g_fWd2i);
    cudaGetSymbolAddress(&dsts[8], g_fWd2h);
    cudaGetSymbolAddress(&dsts[9], g_fWmel);

    int cum = 0;
    for (int m = 0; m < 10; ++m) {
        a.fsrc[m] = (const float*)d_in[srcIdx[m]];
        a.fdst[m] = (uint2*)dsts[m];
        a.fK[m] = Karr[m];
        a.fNT[m] = OParr[m] / 8;
        a.fO[m] = Oarr[m];
        a.fstart[m] = cum;
        cum += (Karr[m] * OParr[m]) / (4 * PREP_TB);
    }
    a.fstart[10] = cum;   // 1668

    a.p2src = (const float*)d_in[5];
    cudaGetSymbolAddress((void**)&a.p2dst, g_tWp2);
    a.enc = enc;
    a.memW = (const float*)d_in[11];
    cudaGetSymbolAddress((void**)&a.pm, g_pmh);
    cudaGetSymbolAddress((void**)&a.ench, g_ench);

    prep_kernel<<<PM_BLOCKS + P2_BLOCKS + cum + ENC_CVT_BLOCKS, PREP_TB>>>(a);

    static bool attr_done = false;
    if (!attr_done) {
        cudaFuncSetAttribute(decoder_kernel,
                             cudaFuncAttributeMaxDynamicSharedMemorySize,
                             (int)sizeof(SD));
        attr_done = true;
    }

    int write_align = (out_size >= BATCH * TD * (INR + TENC)) ? 1 : 0;

    decoder_kernel<<<NGROUPS, TB, sizeof(SD)>>>(
        inputs, memlen,
        (const float*)d_in[4], (const float*)d_in[6],
        (const float*)d_in[8], (const float*)d_in[10],
        (const float*)d_in[13],
        (const float*)d_in[15],
        (const float*)d_in[17], (const float*)d_in[19],
        (const float*)d_in[21], (const float*)d_in[23],
        (const float*)d_in[25],
        (float*)d_out, write_align);
}

// round 14
// speedup vs baseline: 1.2320x; 1.2320x over previous
#include <cuda_runtime.h>
#include <cuda_fp16.h>
#include <cstdint>
#include <cstddef>

#define TB 1024
#define PREP_TB 256
#define BATCH 256
#define ROWS 2
#define NGROUPS (BATCH / ROWS)       // 128 CTAs
#define TENC 200
#define TD 200
#define DMODEL 256
#define INR 400
#define PM_ROWS 16
#define PM_BLOCKS (BATCH * TENC / PM_ROWS)          // 3200
#define ENC_ELEMS (BATCH * TENC * DMODEL)           // 13107200
#define ENC_CVT_BLOCKS (ENC_ELEMS / (PREP_TB * 8))  // 6400

// ------------------------- persistent device scratch -------------------------
__device__ __align__(16) __half g_pmh[ENC_ELEMS];   // processed_memory fp16
__device__ __align__(16) __half g_ench[ENC_ELEMS];  // encoder outputs fp16

// fp16 weights in mma B-fragment layout, dual-n-tile interleaved:
// uint4 at ((kt*NT2 + ntp)*32 + lane) = {b0,b1}(nt=2ntp), {b0,b1}(nt=2ntp+1)
__device__ __align__(16) uint2 g_fWp1[400 * 256 / 4];
__device__ __align__(16) uint2 g_fWaih[384 * 768 / 4];
__device__ __align__(16) uint2 g_fWahh[256 * 768 / 4];
__device__ __align__(16) uint2 g_fWq[256 * 256 / 4];
__device__ __align__(16) uint2 g_fWproj[512 * 256 / 4];
__device__ __align__(16) uint2 g_fWd1i[256 * 768 / 4];
__device__ __align__(16) uint2 g_fWd1h[256 * 768 / 4];
__device__ __align__(16) uint2 g_fWd2i[256 * 768 / 4];
__device__ __align__(16) uint2 g_fWd2h[256 * 768 / 4];
__device__ __align__(16) uint2 g_fWmel[256 * 512 / 4];   // O padded 400->512
// prenet2 keeps the FFMA path: [K][O] fp16
__device__ __align__(16) __half g_tWp2[256 * 128];

// ------------------------- helpers -------------------------
__device__ __forceinline__ float tanh_approx(float x) {
    float y;
    asm("tanh.approx.f32 %0, %1;" : "=f"(y) : "f"(x));
    return y;
}
__device__ __forceinline__ float sigmoidf_(float x) {
    return 1.0f / (1.0f + __expf(-x));
}
__device__ __forceinline__ unsigned long long f2pack(float x, float y) {
    unsigned long long d;
    asm("mov.b64 %0, {%1, %2};" : "=l"(d) : "f"(x), "f"(y));
    return d;
}
__device__ __forceinline__ float2 f2unpack(unsigned long long v) {
    float2 r;
    asm("mov.b64 {%0, %1}, %2;" : "=f"(r.x), "=f"(r.y) : "l"(v));
    return r;
}
__device__ __forceinline__ unsigned long long ffma2(unsigned long long a,
                                                    unsigned long long b,
                                                    unsigned long long c) {
    unsigned long long d;
    asm("fma.rn.f32x2 %0, %1, %2, %3;" : "=l"(d) : "l"(a), "l"(b), "l"(c));
    return d;
}
__device__ __forceinline__ uint32_t pack2h(float lo, float hi) {
    __half2 h = __floats2half2_rn(lo, hi);
    return *reinterpret_cast<uint32_t*>(&h);
}
// m16n8k16 row.col f32 accum
__device__ __forceinline__ void mma16816(float& c0, float& c1, float& c2, float& c3,
                                         uint32_t a0, uint32_t a1, uint32_t a2,
                                         uint32_t a3, uint32_t b0, uint32_t b1) {
    asm volatile(
        "mma.sync.aligned.m16n8k16.row.col.f32.f16.f16.f32 "
        "{%0,%1,%2,%3}, {%4,%5,%6,%7}, {%8,%9}, {%0,%1,%2,%3};"
        : "+f"(c0), "+f"(c1), "+f"(c2), "+f"(c3)
        : "r"(a0), "r"(a1), "r"(a2), "r"(a3), "r"(b0), "r"(b1));
}

// ------------------------- prep kernel ---------------------------------------
struct PrepArgs {
    const float* fsrc[10];
    uint2* fdst[10];
    int fK[10], fNT2[10], fO[10];
    int fstart[11];
    const float* p2src;
    __half* p2dst;
    const float* enc;
    const float* memW;
    __half* pm;
    __half* ench;
};

#define P2_BLOCKS 128   // 256*128/256

__global__ void __launch_bounds__(PREP_TB) prep_kernel(PrepArgs a) {
    int bid = blockIdx.x;
    if (bid < PM_BLOCKS) {
        __shared__ __align__(16) float se[PM_ROWS][DMODEL];
        size_t row0 = (size_t)bid * PM_ROWS;
        for (int i = threadIdx.x; i < PM_ROWS * DMODEL; i += PREP_TB)
            se[i >> 8][i & 255] = a.enc[row0 * DMODEL + i];
        __syncthreads();
        int o = threadIdx.x;
        float acc[PM_ROWS];
#pragma unroll
        for (int r = 0; r < PM_ROWS; ++r) acc[r] = 0.f;
        const float4* W4 = reinterpret_cast<const float4*>(a.memW + (size_t)o * DMODEL);
#pragma unroll 4
        for (int k4 = 0; k4 < DMODEL / 4; ++k4) {
            float4 w = __ldg(&W4[k4]);
#pragma unroll
            for (int r = 0; r < PM_ROWS; ++r) {
                const float* e = &se[r][k4 * 4];
                float s = acc[r];
                s = fmaf(w.x, e[0], s); s = fmaf(w.y, e[1], s);
                s = fmaf(w.z, e[2], s); s = fmaf(w.w, e[3], s);
                acc[r] = s;
            }
        }
#pragma unroll
        for (int r = 0; r < PM_ROWS; ++r)
            a.pm[(row0 + r) * DMODEL + o] = __float2half_rn(acc[r]);
        return;
    }
    int tb = bid - PM_BLOCKS;
    if (tb < P2_BLOCKS) {
        // prenet2 transpose-convert: [O=128][K=256] fp32 -> [K][128] fp16
        int local = tb * PREP_TB + threadIdx.x;
        int k = local >> 7, o = local & 127;
        a.p2dst[local] = __float2half_rn(a.p2src[(size_t)o * 256 + k]);
        return;
    }
    int tb2 = tb - P2_BLOCKS;
    if (tb2 < a.fstart[10]) {
        // fragment prep (dual-n-tile interleaved layout)
        int m = 0;
#pragma unroll
        for (int j = 0; j < 10; ++j)
            if (tb2 >= a.fstart[j + 1]) m = j + 1;
        int i = (tb2 - a.fstart[m]) * PREP_TB + threadIdx.x;   // dest uint2 index
        int half = i & 1;
        int q = i >> 1;
        int lane = q & 31;
        int t3 = q >> 5;
        int NT2 = a.fNT2[m];
        int ntp = t3 % NT2, kt = t3 / NT2;
        int nt = ntp * 2 + half;
        int K = a.fK[m], O = a.fO[m];
        int n = nt * 8 + (lane >> 2);
        int kb = kt * 16 + (lane & 3) * 2;
        const float* src = a.fsrc[m];
        float e0 = 0.f, e1 = 0.f, e2 = 0.f, e3 = 0.f;
        if (n < O) {
            const float* sp = src + (size_t)n * K;
            e0 = sp[kb]; e1 = sp[kb + 1];
            e2 = sp[kb + 8]; e3 = sp[kb + 9];
        }
        uint2 v;
        v.x = pack2h(e0, e1);
        v.y = pack2h(e2, e3);
        a.fdst[m][i] = v;
        return;
    }
    // enc fp32 -> fp16
    int e = tb2 - a.fstart[10];
    size_t i0 = ((size_t)e * PREP_TB + threadIdx.x) * 8;
    const float4* S4 = reinterpret_cast<const float4*>(a.enc + i0);
    float4 f0 = S4[0], f1 = S4[1];
    uint4 outv;
    outv.x = pack2h(f0.x, f0.y);
    outv.y = pack2h(f0.z, f0.w);
    outv.z = pack2h(f1.x, f1.y);
    outv.w = pack2h(f1.z, f1.w);
    *reinterpret_cast<uint4*>(a.ench + i0) = outv;
}

// -------------- mma gemv task (one warp, 256 outputs, 2 rows) ----------------
// frag: interleaved B-fragments; NT2 = OP/16; x2[k]=(row0,row1) fp32 in smem.
// kt0 = first k-tile (16 k each), KT = tiles per task (1 or 2).
// pp -> partials [2][256].
template <int KT>
__device__ __forceinline__ void gemv_mma(const uint2* __restrict__ frag, int NT2,
                                         const float2* __restrict__ x2,
                                         int o0, int kt0,
                                         float* __restrict__ pp) {
    const int lane = threadIdx.x & 31;
    const int tg = (lane & 3) * 2;
    const bool r1 = (lane >> 2) == 1;   // D row 1 lanes use x row1
    uint32_t aLo[KT], aHi[KT];
#pragma unroll
    for (int kt = 0; kt < KT; ++kt) {
        int kk = (kt0 + kt) * 16 + tg;
        float2 xa = x2[kk], xb = x2[kk + 1];
        float2 xc = x2[kk + 8], xd = x2[kk + 9];
        aLo[kt] = pack2h(r1 ? xa.y : xa.x, r1 ? xb.y : xb.x);
        aHi[kt] = pack2h(r1 ? xc.y : xc.x, r1 ? xd.y : xd.x);
    }
    const uint4* fb = reinterpret_cast<const uint4*>(frag) +
                      ((size_t)kt0 * NT2 + (o0 >> 4)) * 32 + lane;
#pragma unroll 8
    for (int ntp = 0; ntp < 16; ++ntp) {
        float c0 = 0.f, c1 = 0.f, c2 = 0.f, c3 = 0.f;
        float e0 = 0.f, e1 = 0.f, e2 = 0.f, e3 = 0.f;
#pragma unroll
        for (int kt = 0; kt < KT; ++kt) {
            uint4 b = __ldg(fb + ((size_t)kt * NT2 + ntp) * 32);
            mma16816(c0, c1, c2, c3, aLo[kt], aLo[kt], aHi[kt], aHi[kt], b.x, b.y);
            mma16816(e0, e1, e2, e3, aLo[kt], aLo[kt], aHi[kt], aHi[kt], b.z, b.w);
        }
        if (lane < 8) {
            int r = lane >> 2;
            *reinterpret_cast<float2*>(pp + r * 256 + (ntp * 2) * 8 + tg) =
                make_float2(c0, c1);
            *reinterpret_cast<float2*>(pp + r * 256 + (ntp * 2 + 1) * 8 + tg) =
                make_float2(e0, e1);
        }
    }
}

// VEC8-layout partial reduce: tasks (o>>8)*NC + c starting at slot tb
template <int NC>
__device__ __forceinline__ float redV8(const float* __restrict__ part, int tb,
                                       int o, int row) {
    const float* p = part + (size_t)(tb + (o >> 8) * NC) * 512 + row * 256 + (o & 255);
    float s = 0.f;
#pragma unroll
    for (int c = 0; c < NC; ++c) s += p[c * 512];
    return s;
}

// -------------- gemv task VEC=4 (128 outputs) for prenet2 --------------------
__device__ __forceinline__ void gemv_task4(const __half* __restrict__ WT, int Ostride,
                                           const float2* __restrict__ x2,
                                           int o0, int k0, int k1,
                                           float* __restrict__ pp) {
    const int lane = threadIdx.x & 31;
    const __half* base = WT + (size_t)k0 * Ostride + o0 + lane * 4;
    unsigned long long a0[2], a1[2];
    a0[0] = a0[1] = a1[0] = a1[1] = 0ull;
#pragma unroll 4
    for (int k = k0; k < k1; ++k) {
        uint2 wv = __ldg(reinterpret_cast<const uint2*>(base));
        base += Ostride;
        float2 w01 = __half22float2(*reinterpret_cast<__half2*>(&wv.x));
        float2 w23 = __half22float2(*reinterpret_cast<__half2*>(&wv.y));
        float2 xv = x2[k];
        unsigned long long xr0 = f2pack(xv.x, xv.x);
        unsigned long long xr1 = f2pack(xv.y, xv.y);
        unsigned long long wA = f2pack(w01.x, w01.y);
        unsigned long long wB = f2pack(w23.x, w23.y);
        a0[0] = ffma2(wA, xr0, a0[0]);
        a1[0] = ffma2(wA, xr1, a1[0]);
        a0[1] = ffma2(wB, xr0, a0[1]);
        a1[1] = ffma2(wB, xr1, a1[1]);
    }
    float2 p0 = f2unpack(a0[0]), p1 = f2unpack(a0[1]);
    float2 q0 = f2unpack(a1[0]), q1 = f2unpack(a1[1]);
    reinterpret_cast<float4*>(pp)[lane] = make_float4(p0.x, p0.y, p1.x, p1.y);
    reinterpret_cast<float4*>(pp + 128)[lane] = make_float4(q0.x, q0.y, q1.x, q1.y);
}

template <int NC>
__device__ __forceinline__ float redV4(const float* __restrict__ part, int tb,
                                       int o, int row) {
    const float* p = part + (size_t)(tb + (o >> 7) * NC) * 256 + row * 128 + (o & 127);
    float s = 0.f;
#pragma unroll
    for (int c = 0; c < NC; ++c) s += p[c * 256];
    return s;
}

// ------------------------- shared memory layout ----------------------------
struct __align__(16) SD {
    float part[60 * 512];     // 122880 B partials (also ctx scratch)
    float2 in2[400];
    float2 p12[256];
    float2 x2[384];           // [0:128)=prenet2, [128:384)=ctx
    float2 cat2[512];
    float2 d2[256];
    float2 ah2[256];
    float2 h12[256];
    float2 h22[256];
    float qT[2][256];
    float sc[2][TENC];
    float v[256];
    int len_s[2];
    float b_p1[256]; float b_p2[128];
    float b_aih[768]; float b_ahh[768];
    float b_proj[256];
    float b_d1i[768]; float b_d1h[768];
    float b_d2i[768]; float b_d2h[768];
    float b_mel[400];
};

// ------------------------- main persistent decoder -------------------------
__global__ void __launch_bounds__(TB, 1) decoder_kernel(
    const float* __restrict__ inputs,
    const int* __restrict__ memlen,
    const float* __restrict__ gb_p1, const float* __restrict__ gb_p2,
    const float* __restrict__ gb_aih, const float* __restrict__ gb_ahh,
    const float* __restrict__ vW,
    const float* __restrict__ gb_proj,
    const float* __restrict__ gb_d1i, const float* __restrict__ gb_d1h,
    const float* __restrict__ gb_d2i, const float* __restrict__ gb_d2h,
    const float* __restrict__ gb_mel,
    float* __restrict__ out, int write_align) {
    extern __shared__ unsigned char smem_raw[];
    SD* s = reinterpret_cast<SD*>(smem_raw);

    const int tid = threadIdx.x;
    const int wid = tid >> 5;
    const int lane = tid & 31;
    const int b0 = blockIdx.x * ROWS;

    // init state + biases + zero first input
    {
        float2 z2 = make_float2(0.f, 0.f);
        if (tid < 256) {
            s->ah2[tid] = z2; s->h12[tid] = z2; s->h22[tid] = z2;
            s->x2[128 + tid] = z2;
            s->v[tid] = vW[tid];
            s->b_p1[tid] = gb_p1[tid];
            s->b_proj[tid] = gb_proj[tid];
        }
        if (tid >= 256 && tid < 384) s->b_p2[tid - 256] = gb_p2[tid - 256];
        if (tid < 768) {
            s->b_aih[tid] = gb_aih[tid]; s->b_ahh[tid] = gb_ahh[tid];
            s->b_d1i[tid] = gb_d1i[tid]; s->b_d1h[tid] = gb_d1h[tid];
            s->b_d2i[tid] = gb_d2i[tid]; s->b_d2h[tid] = gb_d2h[tid];
        }
        if (tid >= 512 && tid < 912) s->b_mel[tid - 512] = gb_mel[tid - 512];
        if (tid < 2) s->len_s[tid] = memlen[b0 + tid];
        if (tid < 400) s->in2[tid] = z2;   // teacher input at t=0 is zeros
    }
    __syncthreads();

    float* outMel = out;
    float* outAl = out + (size_t)BATCH * TD * INR;

    for (int t = 0; t < TD; ++t) {
        // ---- A: prenet1 (O=256, K=400): 25 tasks, 1 k-tile each ----
        if (wid < 25)
            gemv_mma<1>(g_fWp1, 16, s->in2, 0, wid, s->part + (size_t)wid * 512);
        __syncthreads();
        if (tid < 512) {
            int o = tid & 255, row = tid >> 8;
            float r = redV8<25>(s->part, 0, o, row) + s->b_p1[o];
            reinterpret_cast<float*>(&s->p12[o])[row] = fmaxf(r, 0.f);
        } else if (t + 1 < TD) {
            // load teacher-forced input for NEXT step
            for (int i = tid - 512; i < 2 * INR; i += 512) {
                int row = i / INR, o = i - row * INR;
                reinterpret_cast<float*>(&s->in2[o])[row] =
                    inputs[((size_t)(b0 + row) * 1000 + (size_t)t * 5) * 80 + o];
            }
        }
        __syncthreads();

        // ---- B: prenet2 (O=128, K=256): VEC4 FFMA, 32 chunks CH=8 ----
        gemv_task4(g_tWp2, 128, s->p12, 0, wid * 8, wid * 8 + 8,
                   s->part + (size_t)wid * 256);
        __syncthreads();
        if (tid < 256) {
            int o = tid & 127, row = tid >> 7;
            float r = redV4<32>(s->part, 0, o, row) + s->b_p2[o];
            reinterpret_cast<float*>(&s->x2[o])[row] = fmaxf(r, 0.f);
        }
        __syncthreads();

        // ---- C: attn GRU: gi 36 tasks (3 o-tiles x 12 chunks of 2kt, K=384)
        //                  + gh 24 tasks (3 x 8 chunks of 2kt, K=256) ----
        for (int task = wid; task < 60; task += 32) {
            if (task < 36) {
                int ot = task / 12, c = task - ot * 12;
                gemv_mma<2>(g_fWaih, 48, s->x2, ot * 256, c * 2,
                            s->part + (size_t)task * 512);
            } else {
                int t2 = task - 36;
                int ot = t2 >> 3, c = t2 & 7;
                gemv_mma<2>(g_fWahh, 48, s->ah2, ot * 256, c * 2,
                            s->part + (size_t)task * 512);
            }
        }
        __syncthreads();
        if (tid < 512) {
            int o = tid & 255, row = tid >> 8;
            float ir = redV8<12>(s->part, 0, o, row) + s->b_aih[o];
            float iz = redV8<12>(s->part, 0, 256 + o, row) + s->b_aih[256 + o];
            float in = redV8<12>(s->part, 0, 512 + o, row) + s->b_aih[512 + o];
            float hr = redV8<8>(s->part, 36, o, row) + s->b_ahh[o];
            float hz = redV8<8>(s->part, 36, 256 + o, row) + s->b_ahh[256 + o];
            float hn = redV8<8>(s->part, 36, 512 + o, row) + s->b_ahh[512 + o];
            float hp = reinterpret_cast<float*>(&s->ah2[o])[row];
            float rg = sigmoidf_(ir + hr);
            float z = sigmoidf_(iz + hz);
            float n = tanhf(in + rg * hn);
            float h = (1.f - z) * n + z * hp;
            reinterpret_cast<float*>(&s->ah2[o])[row] = h;
            reinterpret_cast<float*>(&s->cat2[o])[row] = h;
        }
        __syncthreads();

        // ---- D: query (O=256, K=256): 16 tasks, 1 kt each ----
        if (wid < 16)
            gemv_mma<1>(g_fWq, 16, s->ah2, 0, wid, s->part + (size_t)wid * 512);
        __syncthreads();
        if (tid < 512) {
            int o = tid & 255, row = tid >> 8;
            s->qT[row][o] = redV8<16>(s->part, 0, o, row);
        }
        __syncthreads();

        // ---- E: Bahdanau scores (fp16 pm) ----
        {
            const float4* V = reinterpret_cast<const float4*>(s->v);
            float4 v0 = V[lane * 2], v1 = V[lane * 2 + 1];
            for (int task = wid; task < 2 * TENC; task += 32) {
                int row = task & 1, tt = task >> 1;
                const uint4* P = reinterpret_cast<const uint4*>(
                    g_pmh + ((size_t)(b0 + row) * TENC + tt) * DMODEL);
                uint4 pv = __ldg(&P[lane]);
                float2 p0 = __half22float2(*reinterpret_cast<__half2*>(&pv.x));
                float2 p1 = __half22float2(*reinterpret_cast<__half2*>(&pv.y));
                float2 p2 = __half22float2(*reinterpret_cast<__half2*>(&pv.z));
                float2 p3 = __half22float2(*reinterpret_cast<__half2*>(&pv.w));
                const float4* Q = reinterpret_cast<const float4*>(s->qT[row]);
                float4 q0 = Q[lane * 2], q1 = Q[lane * 2 + 1];
                float acc = 0.f;
                acc += v0.x * tanh_approx(p0.x + q0.x);
                acc += v0.y * tanh_approx(p0.y + q0.y);
                acc += v0.z * tanh_approx(p1.x + q0.z);
                acc += v0.w * tanh_approx(p1.y + q0.w);
                acc += v1.x * tanh_approx(p2.x + q1.x);
                acc += v1.y * tanh_approx(p2.y + q1.y);
                acc += v1.z * tanh_approx(p3.x + q1.z);
                acc += v1.w * tanh_approx(p3.y + q1.w);
#pragma unroll
                for (int sh = 16; sh; sh >>= 1) acc += __shfl_xor_sync(0xffffffffu, acc, sh);
                if (lane == 0)
                    s->sc[row][tt] = (tt < s->len_s[row]) ? acc : -1e9f;
            }
        }
        __syncthreads();

        // ---- F: softmax per row (warps 0..1) + alignment output ----
        if (wid < 2) {
            int row = wid;
            float m = -1e30f;
            for (int i = lane; i < TENC; i += 32) m = fmaxf(m, s->sc[row][i]);
#pragma unroll
            for (int sh = 16; sh; sh >>= 1) m = fmaxf(m, __shfl_xor_sync(0xffffffffu, m, sh));
            float sum = 0.f;
            for (int i = lane; i < TENC; i += 32) {
                float e = __expf(s->sc[row][i] - m);
                s->sc[row][i] = e;
                sum += e;
            }
#pragma unroll
            for (int sh = 16; sh; sh >>= 1) sum += __shfl_xor_sync(0xffffffffu, sum, sh);
            float inv = 1.f / sum;
            float* ao = outAl + ((size_t)(b0 + row) * TD + t) * TENC;
            for (int i = lane; i < TENC; i += 32) {
                float a = s->sc[row][i] * inv;
                s->sc[row][i] = a;
                if (write_align) ao[i] = a;
            }
        }
        __syncthreads();

        // ---- G: attention context (fp16 enc): g(64) x row(2) x ts(8x25) ----
        {
            int g = tid & 63, row = (tid >> 6) & 1, ts = tid >> 7;
            const uint2* E = reinterpret_cast<const uint2*>(
                                 g_ench + (size_t)(b0 + row) * TENC * DMODEL);
            const float* scp = s->sc[row];
            float4 acc = make_float4(0.f, 0.f, 0.f, 0.f);
            int tt0 = ts * 25;
#pragma unroll 5
            for (int tt = tt0; tt < tt0 + 25; ++tt) {
                float a = scp[tt];
                uint2 ev = __ldg(&E[tt * 64 + g]);
                float2 e0 = __half22float2(*reinterpret_cast<__half2*>(&ev.x));
                float2 e1 = __half22float2(*reinterpret_cast<__half2*>(&ev.y));
                acc.x = fmaf(a, e0.x, acc.x);
                acc.y = fmaf(a, e0.y, acc.y);
                acc.z = fmaf(a, e1.x, acc.z);
                acc.w = fmaf(a, e1.y, acc.w);
            }
            reinterpret_cast<float4*>(s->part)[(ts * 2 + row) * 64 + g] = acc;
        }
        __syncthreads();
        if (tid < 512) {
            int o = tid & 255, row = tid >> 8;
            int gg = o >> 2, comp = o & 3;
            const float* pf = s->part;
            float sv = 0.f;
#pragma unroll
            for (int ts = 0; ts < 8; ++ts)
                sv += pf[((ts * 2 + row) * 64 + gg) * 4 + comp];
            reinterpret_cast<float*>(&s->x2[128 + o])[row] = sv;
            reinterpret_cast<float*>(&s->cat2[256 + o])[row] = sv;
        }
        __syncthreads();

        // ---- H: proj (O=256, K=512): 32 tasks, 1 kt each ----
        gemv_mma<1>(g_fWproj, 16, s->cat2, 0, wid, s->part + (size_t)wid * 512);
        __syncthreads();
        if (tid < 512) {
            int o = tid & 255, row = tid >> 8;
            float r = redV8<32>(s->part, 0, o, row) + s->b_proj[o];
            reinterpret_cast<float*>(&s->d2[o])[row] = r;
        }
        __syncthreads();

        // ---- I/J: decoder GRUs: gi 24 + gh 24 tasks (3 o-tiles x 8 x 2kt) ----
#pragma unroll
        for (int gru = 0; gru < 2; ++gru) {
            const uint2* Wi = gru ? g_fWd2i : g_fWd1i;
            const uint2* Wh = gru ? g_fWd2h : g_fWd1h;
            const float* bi = gru ? s->b_d2i : s->b_d1i;
            const float* bh = gru ? s->b_d2h : s->b_d1h;
            float2* hstate = gru ? s->h22 : s->h12;
            for (int task = wid; task < 48; task += 32) {
                if (task < 24) {
                    int ot = task >> 3, c = task & 7;
                    gemv_mma<2>(Wi, 48, s->d2, ot * 256, c * 2,
                                s->part + (size_t)task * 512);
                } else {
                    int t2 = task - 24;
                    int ot = t2 >> 3, c = t2 & 7;
                    gemv_mma<2>(Wh, 48, hstate, ot * 256, c * 2,
                                s->part + (size_t)task * 512);
                }
            }
            __syncthreads();
            if (tid < 512) {
                int o = tid & 255, row = tid >> 8;
                float ir = redV8<8>(s->part, 0, o, row) + bi[o];
                float iz = redV8<8>(s->part, 0, 256 + o, row) + bi[256 + o];
                float in = redV8<8>(s->part, 0, 512 + o, row) + bi[512 + o];
                float hr = redV8<8>(s->part, 24, o, row) + bh[o];
                float hz = redV8<8>(s->part, 24, 256 + o, row) + bh[256 + o];
                float hn = redV8<8>(s->part, 24, 512 + o, row) + bh[512 + o];
                float hp = reinterpret_cast<float*>(&hstate[o])[row];
                float rg = sigmoidf_(ir + hr);
                float z = sigmoidf_(iz + hz);
                float n = tanhf(in + rg * hn);
                float h = (1.f - z) * n + z * hp;
                reinterpret_cast<float*>(&hstate[o])[row] = h;
                reinterpret_cast<float*>(&s->d2[o])[row] += h;
            }
            __syncthreads();
        }

        // ---- K: mel (O=512 pad, K=256): 2 o-tiles x 16 kt = 32 tasks ----
        {
            int ot = wid >> 4, c = wid & 15;
            gemv_mma<1>(g_fWmel, 32, s->d2, ot * 256, c,
                        s->part + (size_t)wid * 512);
        }
        __syncthreads();
        if (tid < 2 * INR) {
            int row = tid / INR, o = tid - row * INR;
            float r = redV8<16>(s->part, 0, o, row) + s->b_mel[o];
            outMel[((size_t)(b0 + row) * TD + t) * INR + o] = r;
        }
        __syncthreads();
    }
}

// ------------------------- launch -------------------------
extern "C" void kernel_launch(void* const* d_in, const int* in_sizes, int n_in,
                              void* d_out, int out_size) {
    const float* enc = (const float*)d_in[0];
    const float* inputs = (const float*)d_in[1];
    const int* memlen = (const int*)d_in[2];

    PrepArgs a;
    // matrices: p1, aih, ahh, q, proj, d1i, d1h, d2i, d2h, mel
    static const int srcIdx[10] = {3, 7, 9, 12, 14, 16, 18, 20, 22, 24};
    static const int Karr[10] = {400, 384, 256, 256, 512, 256, 256, 256, 256, 256};
    static const int Oarr[10] = {256, 768, 768, 256, 256, 768, 768, 768, 768, 400};
    static const int OParr[10] = {256, 768, 768, 256, 256, 768, 768, 768, 768, 512};

    void* dsts[10];
    cudaGetSymbolAddress(&dsts[0], g_fWp1);
    cudaGetSymbolAddress(&dsts[1], g_fWaih);
    cudaGetSymbolAddress(&dsts[2], g_fWahh);
    cudaGetSymbolAddress(&dsts[3], g_fWq);
    cudaGetSymbolAddress(&dsts[4], g_fWproj);
    cudaGetSymbolAddress(&dsts[5], g_fWd1i);
    cudaGetSymbolAddress(&dsts[6], g_fWd1h);
    cudaGetSymbolAddress(&dsts[7], g_fWd2i);
    cudaGetSymbolAddress(&dsts[8], g_fWd2h);
    cudaGetSymbolAddress(&dsts[9], g_fWmel);

    int cum = 0;
    for (int m = 0; m < 10; ++m) {
        a.fsrc[m] = (const float*)d_in[srcIdx[m]];
        a.fdst[m] = (uint2*)dsts[m];
        a.fK[m] = Karr[m];
        a.fNT2[m] = OParr[m] / 16;
        a.fO[m] = Oarr[m];
        a.fstart[m] = cum;
        cum += (Karr[m] * OParr[m]) / (4 * PREP_TB);
    }
    a.fstart[10] = cum;   // 1668

    a.p2src = (const float*)d_in[5];
    cudaGetSymbolAddress((void**)&a.p2dst, g_tWp2);
    a.enc = enc;
    a.memW = (const float*)d_in[11];
    cudaGetSymbolAddress((void**)&a.pm, g_pmh);
    cudaGetSymbolAddress((void**)&a.ench, g_ench);

    prep_kernel<<<PM_BLOCKS + P2_BLOCKS + cum + ENC_CVT_BLOCKS, PREP_TB>>>(a);

    static bool attr_done = false;
    if (!attr_done) {
        cudaFuncSetAttribute(decoder_kernel,
                             cudaFuncAttributeMaxDynamicSharedMemorySize,
                             (int)sizeof(SD));
        attr_done = true;
    }

    int write_align = (out_size >= BATCH * TD * (INR + TENC)) ? 1 : 0;

    decoder_kernel<<<NGROUPS, TB, sizeof(SD)>>>(
        inputs, memlen,
        (const float*)d_in[4], (const float*)d_in[6],
        (const float*)d_in[8], (const float*)d_in[10],
        (const float*)d_in[13],
        (const float*)d_in[15],
        (const float*)d_in[17], (const float*)d_in[19],
        (const float*)d_in[21], (const float*)d_in[23],
        (const float*)d_in[25],
        (float*)d_out, write_align);
}